// round 10
// baseline (speedup 1.0000x reference)
#include <cuda_runtime.h>
#include <math.h>

#define B_   128
#define I_   512
#define H_   512
#define SIXH 3072
#define BH   (B_*H_)          // 65536
#define BHH  (B_*H_*H_)       // 33554432
#define KSPLIT 8
#define KC   (I_/KSPLIT)      // 64

// ---------------- scratch (no allocations allowed) ----------------
__device__ float g_part[KSPLIT * B_ * SIXH]; // split-K partial gates
__device__ float g_q[BH];            // summed q gate (for K3)
__device__ float g_f[BH];            // f_t
__device__ float g_s[BH];            // i_t * v * k_t
__device__ float g_o[BH];            // sigmoid(og)
__device__ float g_nq[B_];           // dot(n_t, q) per batch

// ---------------- K1: partial gates = x @ W^T  (split-K, double-buffered) ----
#define BM 64
#define BN 64
#define BK 16
__global__ void __launch_bounds__(256)
gemm_gates(const float* __restrict__ x, const float* __restrict__ W)
{
    __shared__ float As[2][BK][BM];
    __shared__ float Bs[2][BK][BN];

    const int m0 = blockIdx.y * BM;           // batch tile (2)
    const int n0 = blockIdx.x * BN;           // gate-col tile (48)
    const int kz = blockIdx.z;                // split-K slice (8)
    const int tid = threadIdx.x;              // 256 threads
    const int tx = tid & 15;
    const int ty = tid >> 4;

    float acc[4][4];
#pragma unroll
    for (int i = 0; i < 4; i++)
#pragma unroll
        for (int j = 0; j < 4; j++) acc[i][j] = 0.f;

    const int lr = tid >> 2;    // 0..63 row within tile
    const int lq = tid & 3;     // 0..3  float4 within BK

    const int kbeg = kz * KC;
    const int NIT = KC / BK;    // 4

    // prologue: stage chunk 0
    float4 a = *(const float4*)(x + (m0 + lr) * I_ + kbeg + lq * 4);
    float4 w = *(const float4*)(W + (n0 + lr) * I_ + kbeg + lq * 4);
    As[0][lq*4+0][lr] = a.x; As[0][lq*4+1][lr] = a.y;
    As[0][lq*4+2][lr] = a.z; As[0][lq*4+3][lr] = a.w;
    Bs[0][lq*4+0][lr] = w.x; Bs[0][lq*4+1][lr] = w.y;
    Bs[0][lq*4+2][lr] = w.z; Bs[0][lq*4+3][lr] = w.w;
    __syncthreads();

#pragma unroll
    for (int it = 0; it < NIT; it++) {
        const int cur = it & 1;
        // prefetch next chunk into registers (latency hidden under compute)
        if (it + 1 < NIT) {
            const int k0 = kbeg + (it + 1) * BK;
            a = *(const float4*)(x + (m0 + lr) * I_ + k0 + lq * 4);
            w = *(const float4*)(W + (n0 + lr) * I_ + k0 + lq * 4);
        }

#pragma unroll
        for (int kk = 0; kk < BK; kk++) {
            float av[4], bv[4];
#pragma unroll
            for (int i = 0; i < 4; i++) av[i] = As[cur][kk][ty*4 + i];
#pragma unroll
            for (int j = 0; j < 4; j++) bv[j] = Bs[cur][kk][tx*4 + j];
#pragma unroll
            for (int i = 0; i < 4; i++)
#pragma unroll
                for (int j = 0; j < 4; j++)
                    acc[i][j] = fmaf(av[i], bv[j], acc[i][j]);
        }
        __syncthreads();

        if (it + 1 < NIT) {
            const int nxt = (it + 1) & 1;
            As[nxt][lq*4+0][lr] = a.x; As[nxt][lq*4+1][lr] = a.y;
            As[nxt][lq*4+2][lr] = a.z; As[nxt][lq*4+3][lr] = a.w;
            Bs[nxt][lq*4+0][lr] = w.x; Bs[nxt][lq*4+1][lr] = w.y;
            Bs[nxt][lq*4+2][lr] = w.z; Bs[nxt][lq*4+3][lr] = w.w;
            __syncthreads();
        }
    }

    float* dst = g_part + (size_t)kz * B_ * SIXH;
#pragma unroll
    for (int i = 0; i < 4; i++) {
        const int m = m0 + ty*4 + i;
#pragma unroll
        for (int j = 0; j < 4; j++) {
            const int n = n0 + tx*4 + j;
            dst[m * SIXH + n] = acc[i][j];
        }
    }
}

// ---------------- K2: reduce split-K + bias + gate transforms ----------------
// grid = B_ blocks, 512 threads (one per h)
__global__ void gate_transform(const float* __restrict__ m_prev,
                               const float* __restrict__ n_prev,
                               const float* __restrict__ bias,
                               float* __restrict__ out)
{
    const int b = blockIdx.x;
    const int h = threadIdx.x;

    float ig = bias[h];
    float fg = bias[H_   + h];
    float og = bias[2*H_ + h];
    float q  = bias[3*H_ + h];
    float k  = bias[4*H_ + h];
    float v  = bias[5*H_ + h];
#pragma unroll
    for (int kz = 0; kz < KSPLIT; kz++) {
        const float* g = g_part + (size_t)kz * B_ * SIXH + b * SIXH;
        ig += g[h];
        fg += g[H_   + h];
        og += g[2*H_ + h];
        q  += g[3*H_ + h];
        k  += g[4*H_ + h];
        v  += g[5*H_ + h];
    }

    const float inv_sqrt_h = 0.044194173824159216f; // 1/sqrt(512)
    const float mp = m_prev[b*H_ + h];
    const float m_t = fmaxf(fg + mp, ig);
    const float i_t = __expf(ig - m_t);
    const float f_t = __expf(fg + mp - m_t);
    const float k_t = k * inv_sqrt_h;
    const float n_t = f_t * n_prev[b*H_ + h] + i_t * k_t;

    const int idx = b*H_ + h;
    g_q[idx] = q;
    g_f[idx] = f_t;
    g_s[idx] = i_t * v * k_t;
    g_o[idx] = 1.f / (1.f + __expf(-og));

    // outputs: [h_t | C_t | m_t | n_t]
    out[BH + BHH + idx]      = m_t;   // m_t
    out[BH + BHH + BH + idx] = n_t;   // n_t

    // nq[b] = sum_h n_t * q  (block reduction, 512 threads = 16 warps)
    float p = n_t * q;
#pragma unroll
    for (int off = 16; off > 0; off >>= 1)
        p += __shfl_down_sync(0xffffffff, p, off);
    __shared__ float warp_s[16];
    if ((h & 31) == 0) warp_s[h >> 5] = p;
    __syncthreads();
    if (h < 32) {
        float t = (h < 16) ? warp_s[h] : 0.f;
#pragma unroll
        for (int off = 8; off > 0; off >>= 1)
            t += __shfl_down_sync(0xffffffff, t, off);
        if (h == 0) g_nq[b] = t;
    }
}

// ---------------- K3: C_t = f*C_prev + s, fused Cq = C_t @ q, h_t ------------
// One warp per C row; 8 rows per block share smem-cached q[b].
#define ROWS_PER_BLK 8
__global__ void state_update(const float* __restrict__ C_prev,
                             float* __restrict__ out)
{
    __shared__ float qs[H_];
    const int b      = blockIdx.x >> 6;          // /64
    const int i_base = (blockIdx.x & 63) * ROWS_PER_BLK;
    const int tid    = threadIdx.x;
    const int warp   = tid >> 5;
    const int lane   = tid & 31;

    qs[tid]       = g_q[b * H_ + tid];
    qs[tid + 256] = g_q[b * H_ + tid + 256];
    __syncthreads();

    const int i   = i_base + warp;
    const int row = b * H_ + i;
    const float f = g_f[row];
    const float s = g_s[row];

    const float4* Cin  = (const float4*)(C_prev + (size_t)row * H_);
    float4*       Cout = (float4*)(out + BH + (size_t)row * H_);

    float acc = 0.f;
#pragma unroll
    for (int t = 0; t < 4; t++) {
        const int j4 = lane + t * 32;          // float4 index 0..127
        float4 c = __ldcs(Cin + j4);           // streaming: no reuse
        c.x = fmaf(f, c.x, s);
        c.y = fmaf(f, c.y, s);
        c.z = fmaf(f, c.z, s);
        c.w = fmaf(f, c.w, s);
        __stcs(Cout + j4, c);                  // streaming store
        const int j = j4 * 4;
        acc = fmaf(c.x, qs[j],   acc);
        acc = fmaf(c.y, qs[j+1], acc);
        acc = fmaf(c.z, qs[j+2], acc);
        acc = fmaf(c.w, qs[j+3], acc);
    }
#pragma unroll
    for (int off = 16; off > 0; off >>= 1)
        acc += __shfl_down_sync(0xffffffff, acc, off);

    if (lane == 0) {
        const float denom = fmaxf(fabsf(g_nq[b]), 1e-6f);
        out[row] = g_o[row] * (acc / denom);   // h_t
    }
}

// ---------------- launch ------------------------------------------------------
extern "C" void kernel_launch(void* const* d_in, const int* in_sizes, int n_in,
                              void* d_out, int out_size)
{
    const float* x      = (const float*)d_in[0];
    // d_in[1] = h_prev (unused by the reference math)
    const float* C_prev = (const float*)d_in[2];
    const float* m_prev = (const float*)d_in[3];
    const float* n_prev = (const float*)d_in[4];
    const float* W      = (const float*)d_in[5];
    const float* bias   = (const float*)d_in[6];
    float* out = (float*)d_out;

    dim3 g1(SIXH / BN, B_ / BM, KSPLIT);          // 48 x 2 x 8 = 768 blocks
    gemm_gates<<<g1, 256>>>(x, W);
    gate_transform<<<B_, H_>>>(m_prev, n_prev, bias, out);
    state_update<<<B_ * H_ / ROWS_PER_BLK, 256>>>(C_prev, out);
}

// round 11
// speedup vs baseline: 1.2998x; 1.2998x over previous
#include <cuda_runtime.h>
#include <math.h>
#include <stdint.h>

#define B_   128
#define I_   512
#define H_   512
#define SIXH 3072
#define BH   (B_*H_)          // 65536
#define BHH  (B_*H_*H_)       // 33554432
#define KSPLIT 4
#define KC   (I_/KSPLIT)      // 128

// ---------------- scratch (no allocations allowed) ----------------
__device__ float g_part[KSPLIT * B_ * SIXH]; // split-K partial gates
__device__ float g_q[BH];            // summed q gate (for K3)
__device__ float g_f[BH];            // f_t
__device__ float g_s[BH];            // i_t * v * k_t
__device__ float g_o[BH];            // sigmoid(og)
__device__ float g_nq[B_];           // dot(n_t, q) per batch

// packed f32x2 helpers (sm_103a FFMA2 path)
#define FMA2(c, a, b) \
    asm("fma.rn.f32x2 %0, %1, %2, %0;" : "+l"(c) : "l"(a), "l"(b))
#define PACK2(out, lo, hi) \
    asm("mov.b64 %0, {%1, %2};" : "=l"(out) : "f"(lo), "f"(hi))
#define UNPACK2(lo, hi, in) \
    asm("mov.b64 {%0, %1}, %2;" : "=f"(lo), "=f"(hi) : "l"(in))

// ---------------- K1: partial gates = x @ W^T  (split-K, FFMA2 inner) --------
#define BM 64
#define BN 64
#define BK 16
__global__ void __launch_bounds__(256)
gemm_gates(const float* __restrict__ x, const float* __restrict__ W)
{
    __shared__ float As[BK][BM];
    __shared__ float Bs[BK][BN];

    const int m0 = blockIdx.y * BM;           // batch tile (2)
    const int n0 = blockIdx.x * BN;           // gate-col tile (48)
    const int kz = blockIdx.z;                // split-K slice (4)
    const int tid = threadIdx.x;              // 256 threads
    const int tx = tid & 15;
    const int ty = tid >> 4;

    // acc as packed f32x2: [i][j-pair]  (i: 4 rows, j: 2 pairs = 4 cols)
    unsigned long long acc2[4][2];
#pragma unroll
    for (int i = 0; i < 4; i++) { acc2[i][0] = 0ULL; acc2[i][1] = 0ULL; }

    const int lr = tid >> 2;    // 0..63 row within tile
    const int lq = tid & 3;     // 0..3  float4 within BK

    const int kbeg = kz * KC;
#pragma unroll 1
    for (int k0 = kbeg; k0 < kbeg + KC; k0 += BK) {
        float4 a = *(const float4*)(x + (m0 + lr) * I_ + k0 + lq * 4);
        As[lq*4+0][lr] = a.x; As[lq*4+1][lr] = a.y;
        As[lq*4+2][lr] = a.z; As[lq*4+3][lr] = a.w;
        float4 w = *(const float4*)(W + (n0 + lr) * I_ + k0 + lq * 4);
        Bs[lq*4+0][lr] = w.x; Bs[lq*4+1][lr] = w.y;
        Bs[lq*4+2][lr] = w.z; Bs[lq*4+3][lr] = w.w;
        __syncthreads();

#pragma unroll
        for (int kk = 0; kk < BK; kk++) {
            const float4 avv = *(const float4*)&As[kk][ty*4];
            const float4 bvv = *(const float4*)&Bs[kk][tx*4];
            unsigned long long b01, b23, ad;
            PACK2(b01, bvv.x, bvv.y);
            PACK2(b23, bvv.z, bvv.w);
            PACK2(ad, avv.x, avv.x);
            FMA2(acc2[0][0], ad, b01); FMA2(acc2[0][1], ad, b23);
            PACK2(ad, avv.y, avv.y);
            FMA2(acc2[1][0], ad, b01); FMA2(acc2[1][1], ad, b23);
            PACK2(ad, avv.z, avv.z);
            FMA2(acc2[2][0], ad, b01); FMA2(acc2[2][1], ad, b23);
            PACK2(ad, avv.w, avv.w);
            FMA2(acc2[3][0], ad, b01); FMA2(acc2[3][1], ad, b23);
        }
        __syncthreads();
    }

    float* dst = g_part + (size_t)kz * B_ * SIXH;
#pragma unroll
    for (int i = 0; i < 4; i++) {
        const int m = m0 + ty*4 + i;
        float4 r;
        UNPACK2(r.x, r.y, acc2[i][0]);
        UNPACK2(r.z, r.w, acc2[i][1]);
        *(float4*)(dst + m * SIXH + n0 + tx*4) = r;
    }
}

// ---------------- K2: reduce split-K + bias + gate transforms ----------------
// grid = B_ blocks, 512 threads (one per h)
__global__ void gate_transform(const float* __restrict__ m_prev,
                               const float* __restrict__ n_prev,
                               const float* __restrict__ bias,
                               float* __restrict__ out)
{
    const int b = blockIdx.x;
    const int h = threadIdx.x;

    float ig = bias[h];
    float fg = bias[H_   + h];
    float og = bias[2*H_ + h];
    float q  = bias[3*H_ + h];
    float k  = bias[4*H_ + h];
    float v  = bias[5*H_ + h];
#pragma unroll
    for (int kz = 0; kz < KSPLIT; kz++) {
        const float* g = g_part + (size_t)kz * B_ * SIXH + b * SIXH;
        ig += g[h];
        fg += g[H_   + h];
        og += g[2*H_ + h];
        q  += g[3*H_ + h];
        k  += g[4*H_ + h];
        v  += g[5*H_ + h];
    }

    const float inv_sqrt_h = 0.044194173824159216f; // 1/sqrt(512)
    const float mp = m_prev[b*H_ + h];
    const float m_t = fmaxf(fg + mp, ig);
    const float i_t = __expf(ig - m_t);
    const float f_t = __expf(fg + mp - m_t);
    const float k_t = k * inv_sqrt_h;
    const float n_t = f_t * n_prev[b*H_ + h] + i_t * k_t;

    const int idx = b*H_ + h;
    g_q[idx] = q;
    g_f[idx] = f_t;
    g_s[idx] = i_t * v * k_t;
    g_o[idx] = 1.f / (1.f + __expf(-og));

    // outputs: [h_t | C_t | m_t | n_t]
    out[BH + BHH + idx]      = m_t;   // m_t
    out[BH + BHH + BH + idx] = n_t;   // n_t

    // nq[b] = sum_h n_t * q  (block reduction, 512 threads = 16 warps)
    float p = n_t * q;
#pragma unroll
    for (int off = 16; off > 0; off >>= 1)
        p += __shfl_down_sync(0xffffffff, p, off);
    __shared__ float warp_s[16];
    if ((h & 31) == 0) warp_s[h >> 5] = p;
    __syncthreads();
    if (h < 32) {
        float t = (h < 16) ? warp_s[h] : 0.f;
#pragma unroll
        for (int off = 8; off > 0; off >>= 1)
            t += __shfl_down_sync(0xffffffff, t, off);
        if (h == 0) g_nq[b] = t;
    }
}

// ---------------- K3: C_t = f*C_prev + s, fused Cq = C_t @ q, h_t ------------
// One warp per C row; 8 rows per block share smem-cached q[b].
#define ROWS_PER_BLK 8
__global__ void state_update(const float* __restrict__ C_prev,
                             float* __restrict__ out)
{
    __shared__ float qs[H_];
    const int b      = blockIdx.x >> 6;          // /64
    const int i_base = (blockIdx.x & 63) * ROWS_PER_BLK;
    const int tid    = threadIdx.x;
    const int warp   = tid >> 5;
    const int lane   = tid & 31;

    qs[tid]       = g_q[b * H_ + tid];
    qs[tid + 256] = g_q[b * H_ + tid + 256];
    __syncthreads();

    const int i   = i_base + warp;
    const int row = b * H_ + i;
    const float f = g_f[row];
    const float s = g_s[row];

    const float4* Cin  = (const float4*)(C_prev + (size_t)row * H_);
    float4*       Cout = (float4*)(out + BH + (size_t)row * H_);

    float acc = 0.f;
#pragma unroll
    for (int t = 0; t < 4; t++) {
        const int j4 = lane + t * 32;          // float4 index 0..127
        float4 c = __ldcs(Cin + j4);           // streaming: no reuse
        c.x = fmaf(f, c.x, s);
        c.y = fmaf(f, c.y, s);
        c.z = fmaf(f, c.z, s);
        c.w = fmaf(f, c.w, s);
        __stcs(Cout + j4, c);                  // streaming store
        const int j = j4 * 4;
        acc = fmaf(c.x, qs[j],   acc);
        acc = fmaf(c.y, qs[j+1], acc);
        acc = fmaf(c.z, qs[j+2], acc);
        acc = fmaf(c.w, qs[j+3], acc);
    }
#pragma unroll
    for (int off = 16; off > 0; off >>= 1)
        acc += __shfl_down_sync(0xffffffff, acc, off);

    if (lane == 0) {
        const float denom = fmaxf(fabsf(g_nq[b]), 1e-6f);
        out[row] = g_o[row] * (acc / denom);   // h_t
    }
}

// ---------------- launch ------------------------------------------------------
extern "C" void kernel_launch(void* const* d_in, const int* in_sizes, int n_in,
                              void* d_out, int out_size)
{
    const float* x      = (const float*)d_in[0];
    // d_in[1] = h_prev (unused by the reference math)
    const float* C_prev = (const float*)d_in[2];
    const float* m_prev = (const float*)d_in[3];
    const float* n_prev = (const float*)d_in[4];
    const float* W      = (const float*)d_in[5];
    const float* bias   = (const float*)d_in[6];
    float* out = (float*)d_out;

    dim3 g1(SIXH / BN, B_ / BM, KSPLIT);          // 48 x 2 x 4 = 384 blocks
    gemm_gates<<<g1, 256>>>(x, W);
    gate_transform<<<B_, H_>>>(m_prev, n_prev, bias, out);
    state_update<<<B_ * H_ / ROWS_PER_BLK, 256>>>(C_prev, out);
}